// round 1
// baseline (speedup 1.0000x reference)
#include <cuda_runtime.h>
#include <cstdint>

typedef unsigned long long u64;

#define BLOCK 256
#define PAIRS 256
#define ROWS  512
#define NF    63
#define PADF2 65   // float2 stride per row-pair in smem (conflict-free: 130 words, 130 mod 32 = 2)

__device__ __forceinline__ u64 ffma2(u64 a, u64 b, u64 c) {
    u64 d;
    asm("fma.rn.f32x2 %0, %1, %2, %3;" : "=l"(d) : "l"(a), "l"(b), "l"(c));
    return d;
}
__device__ __forceinline__ u64 pack2(float x, float y) {
    u64 r; asm("mov.b64 %0, {%1, %2};" : "=l"(r) : "f"(x), "f"(y)); return r;
}
__device__ __forceinline__ void unpack2(u64 v, float& x, float& y) {
    asm("mov.b64 {%0, %1}, %2;" : "=f"(x), "=f"(y) : "l"(v));
}

__global__ __launch_bounds__(BLOCK, 1)
void hybrid_mlp_kernel(const float* __restrict__ x_q,
                       const float* __restrict__ x_c,
                       const float* __restrict__ q_params,
                       const float* __restrict__ w1, const float* __restrict__ b1,
                       const float* __restrict__ w2, const float* __restrict__ b2,
                       const float* __restrict__ w3, const float* __restrict__ b3,
                       float* __restrict__ out, int B)
{
    extern __shared__ unsigned char smem_raw[];
    float2* combp = (float2*)smem_raw;                  // PAIRS * PADF2 float2
    float2* w1d   = combp + PAIRS * PADF2;              // [j=64][o=32] dup weights
    float2* w2d   = w1d + 64 * 32;                      // [j=32][o=16]
    float2* w3d   = w2d + 32 * 16;                      // [16]
    float2* b1d   = w3d + 16;                           // [32]
    float2* b2d   = b1d + 32;                           // [16]
    float*  xqs   = (float*)(b2d + 16);                 // ROWS*3 floats

    const int tid  = threadIdx.x;
    const long base = (long)blockIdx.x * ROWS;
    const int rows = min(ROWS, B - (int)base);

    // ---- stage weights, duplicated into f32x2 lanes ----
    for (int i = tid; i < 2048; i += BLOCK) {           // w1: [32 out][64 in] -> w1d[j][o]
        int o = i >> 6, j = i & 63;
        float w = w1[i];
        w1d[j * 32 + o] = make_float2(w, w);
    }
    for (int i = tid; i < 512; i += BLOCK) {            // w2: [16 out][32 in] -> w2d[j][o]
        int o = i >> 5, j = i & 31;
        float w = w2[i];
        w2d[j * 16 + o] = make_float2(w, w);
    }
    if (tid < 16) { float w = w3[tid]; w3d[tid] = make_float2(w, w); }
    if (tid < 32) { float v = b1[tid]; b1d[tid] = make_float2(v, v); }
    if (tid < 16) { float v = b2[tid]; b2d[tid] = make_float2(v, v); }

    // ---- stage x_c (coalesced) into pair-packed smem tile ----
    // comb[0] = q feature (filled later), comb[1..63] = x_c row
    const float* xc_blk = x_c + base * NF;
    if (rows == ROWS) {
        const float4* src = (const float4*)xc_blk;      // 512*63 % 4 == 0, base 16B-aligned
        for (int i = tid; i < ROWS * NF / 4; i += BLOCK) {
            float4 v = src[i];
            int lin = i * 4;
            float vv[4] = {v.x, v.y, v.z, v.w};
            #pragma unroll
            for (int e = 0; e < 4; e++) {
                int l = lin + e;
                int r = l / NF;
                int c = l - r * NF;
                ((float*)(combp + (r >> 1) * PADF2 + (c + 1)))[r & 1] = vv[e];
            }
        }
    } else {
        for (int l = tid; l < rows * NF; l += BLOCK) {
            int r = l / NF, c = l - r * NF;
            ((float*)(combp + (r >> 1) * PADF2 + (c + 1)))[r & 1] = xc_blk[l];
        }
    }

    // ---- stage x_q (coalesced) ----
    const float* xq_blk = x_q + base * 3;
    for (int i = tid; i < rows * 3; i += BLOCK) xqs[i] = xq_blk[i];
    __syncthreads();

    // ---- quantum feature: <Z0> = cos(x1+p1)*cos(x2+p2) (qubit 0 cancels) ----
    const float qp1 = q_params[1], qp2 = q_params[2];
    const int pairs = (rows + 1) >> 1;
    if (tid < pairs) {
        int rA = 2 * tid, rB = 2 * tid + 1;
        float qA = cosf(xqs[rA * 3 + 1] + qp1) * cosf(xqs[rA * 3 + 2] + qp2);
        float qB = 0.0f;
        if (rB < rows)
            qB = cosf(xqs[rB * 3 + 1] + qp1) * cosf(xqs[rB * 3 + 2] + qp2);
        combp[tid * PADF2] = make_float2(qA, qB);
    }
    __syncthreads();

    // ---- fused MLP, two rows per thread via packed f32x2 FMA ----
    if (tid < pairs) {
        const u64* cp  = (const u64*)(combp + tid * PADF2);
        const u64* b1p = (const u64*)b1d;

        u64 acc[32];
        #pragma unroll
        for (int o = 0; o < 32; o++) acc[o] = b1p[o];

        #pragma unroll 4
        for (int j = 0; j < 64; j++) {
            u64 c2 = cp[j];                              // LDS.64, conflict-free
            const ulonglong2* wr = (const ulonglong2*)(w1d + j * 32);
            #pragma unroll
            for (int o = 0; o < 16; o++) {
                ulonglong2 wv = wr[o];                   // LDS.128 broadcast
                acc[2 * o]     = ffma2(c2, wv.x, acc[2 * o]);
                acc[2 * o + 1] = ffma2(c2, wv.y, acc[2 * o + 1]);
            }
        }

        // relu -> h1 (reuse acc)
        #pragma unroll
        for (int o = 0; o < 32; o++) {
            float x, y; unpack2(acc[o], x, y);
            acc[o] = pack2(fmaxf(x, 0.0f), fmaxf(y, 0.0f));
        }

        const u64* b2p = (const u64*)b2d;
        u64 acc2[16];
        #pragma unroll
        for (int o = 0; o < 16; o++) acc2[o] = b2p[o];

        #pragma unroll 4
        for (int j = 0; j < 32; j++) {
            u64 h = acc[j];
            const ulonglong2* wr = (const ulonglong2*)(w2d + j * 16);
            #pragma unroll
            for (int o = 0; o < 8; o++) {
                ulonglong2 wv = wr[o];
                acc2[2 * o]     = ffma2(h, wv.x, acc2[2 * o]);
                acc2[2 * o + 1] = ffma2(h, wv.y, acc2[2 * o + 1]);
            }
        }

        // relu + layer 3 (dot with w3)
        float b3v = *b3;
        u64 y2 = pack2(b3v, b3v);
        const u64* w3p = (const u64*)w3d;
        #pragma unroll
        for (int o = 0; o < 16; o++) {
            float x, y; unpack2(acc2[o], x, y);
            y2 = ffma2(pack2(fmaxf(x, 0.0f), fmaxf(y, 0.0f)), w3p[o], y2);
        }

        float yx, yy; unpack2(y2, yx, yy);
        long gp = base + 2L * tid;
        if (2 * tid + 1 < rows) {
            *(float2*)(out + gp) = make_float2(yx, yy);  // coalesced STG.64
        } else {
            out[gp] = yx;
        }
    }
}

extern "C" void kernel_launch(void* const* d_in, const int* in_sizes, int n_in,
                              void* d_out, int out_size) {
    const float* x_q = (const float*)d_in[0];
    const float* x_c = (const float*)d_in[1];
    const float* qp  = (const float*)d_in[2];
    const float* w1  = (const float*)d_in[3];
    const float* b1  = (const float*)d_in[4];
    const float* w2  = (const float*)d_in[5];
    const float* b2  = (const float*)d_in[6];
    const float* w3  = (const float*)d_in[7];
    const float* b3  = (const float*)d_in[8];

    int B = in_sizes[0] / 3;

    // smem: combp + weights + biases + xq scratch
    int smem = (PAIRS * PADF2 + 64 * 32 + 32 * 16 + 16 + 32 + 16) * (int)sizeof(float2)
               + ROWS * 3 * (int)sizeof(float);
    cudaFuncSetAttribute(hybrid_mlp_kernel,
                         cudaFuncAttributeMaxDynamicSharedMemorySize, smem);

    int nblk = (B + ROWS - 1) / ROWS;
    hybrid_mlp_kernel<<<nblk, BLOCK, smem>>>(x_q, x_c, qp, w1, b1, w2, b2, w3, b3,
                                             (float*)d_out, B);
}

// round 2
// speedup vs baseline: 1.5125x; 1.5125x over previous
#include <cuda_runtime.h>
#include <cstdint>

typedef unsigned long long u64;

#define BLOCK   256
#define WARPS   8
#define PAIRS   128              // 256 rows per block
#define ROWS    256
#define NF      63
#define PPW     16               // pairs per warp
#define SWEEPS  8                // 2 pairs per sweep

// smem byte offsets
#define TILE_OFF   0             // u64 tile[128][64]        65536
#define HTILE_OFF  65536         // u64 htile[128][32]       32768
#define W1S_OFF    98304         // float w1s[32*65]          8320
#define W2S_OFF    106624        // u64  w2s[32*16]           4096
#define W3S_OFF    110720        // u64  w3s[16]               128
#define B2S_OFF    110848        // u64  b2s[16]               128
#define XQS_OFF    110976        // float xqs[256*3]          3072
#define SMEM_TOTAL 114048

__device__ __forceinline__ u64 ffma2(u64 a, u64 b, u64 c) {
    u64 d; asm("fma.rn.f32x2 %0, %1, %2, %3;" : "=l"(d) : "l"(a), "l"(b), "l"(c));
    return d;
}
__device__ __forceinline__ u64 add2(u64 a, u64 b) {
    u64 d; asm("add.rn.f32x2 %0, %1, %2;" : "=l"(d) : "l"(a), "l"(b)); return d;
}
__device__ __forceinline__ u64 mul2(u64 a, u64 b) {
    u64 d; asm("mul.rn.f32x2 %0, %1, %2;" : "=l"(d) : "l"(a), "l"(b)); return d;
}
__device__ __forceinline__ u64 pack2(float x, float y) {
    u64 r; asm("mov.b64 %0, {%1, %2};" : "=l"(r) : "f"(x), "f"(y)); return r;
}
__device__ __forceinline__ u64 dup2(float x) {
    u64 r; asm("mov.b64 %0, {%1, %1};" : "=l"(r) : "f"(x)); return r;
}
__device__ __forceinline__ void unpack2(u64 v, float& x, float& y) {
    asm("mov.b64 {%0, %1}, %2;" : "=f"(x), "=f"(y) : "l"(v));
}
__device__ __forceinline__ u64 relu2(u64 v) {
    float x, y; unpack2(v, x, y);
    return pack2(fmaxf(x, 0.0f), fmaxf(y, 0.0f));
}

__global__ __launch_bounds__(BLOCK, 2)
void hybrid_mlp_kernel(const float* __restrict__ x_q,
                       const float* __restrict__ x_c,
                       const float* __restrict__ q_params,
                       const float* __restrict__ w1, const float* __restrict__ b1,
                       const float* __restrict__ w2, const float* __restrict__ b2,
                       const float* __restrict__ w3, const float* __restrict__ b3,
                       float* __restrict__ out, int B)
{
    extern __shared__ unsigned char smem[];
    u64*   tile  = (u64*)(smem + TILE_OFF);    // [pair][64] packed (rowA,rowB) features
    u64*   htile = (u64*)(smem + HTILE_OFF);   // [pair][32] layer-1 activations (pairs)
    float* w1s   = (float*)(smem + W1S_OFF);   // [32][65] padded
    u64*   w2s   = (u64*)(smem + W2S_OFF);     // [j=32][o=16] duplicated
    u64*   w3s   = (u64*)(smem + W3S_OFF);     // [16] duplicated
    u64*   b2s   = (u64*)(smem + B2S_OFF);     // [16] duplicated
    float* xqs   = (float*)(smem + XQS_OFF);   // [256*3]

    const int tid  = threadIdx.x;
    const int lane = tid & 31;
    const int warp = tid >> 5;
    const long base = (long)blockIdx.x * ROWS;
    const int rows = (B - (int)base < ROWS) ? (B - (int)base) : ROWS;

    // ---- stage small weights ----
    for (int i = tid; i < 2048; i += BLOCK) {          // w1 [32][64] -> padded
        w1s[(i >> 6) * 65 + (i & 63)] = w1[i];
    }
    for (int i = tid; i < 512; i += BLOCK) {           // w2 [16][32] -> w2s[j][o] dup
        int o = i >> 5, j = i & 31;
        w2s[j * 16 + o] = dup2(w2[i]);
    }
    if (tid < 16) w3s[tid] = dup2(w3[tid]);
    if (tid < 16) b2s[tid] = dup2(b2[tid]);

    // ---- stage x_q ----
    const float* xq_blk = x_q + base * 3;
    if (rows == ROWS) {
        for (int i = tid; i < ROWS * 3; i += BLOCK) xqs[i] = xq_blk[i];
    } else {
        for (int i = tid; i < ROWS * 3; i += BLOCK)
            xqs[i] = (i < rows * 3) ? xq_blk[i] : 0.0f;
    }

    // ---- stage x_c into pair-packed tile (coalesced float4 loads) ----
    const float* xc_blk = x_c + base * NF;
    if (rows == ROWS) {
        const float4* src = (const float4*)xc_blk;     // 256*63 % 4 == 0, 16B-aligned
        for (int i = tid; i < ROWS * NF / 4; i += BLOCK) {
            float4 v = src[i];
            int lin = i * 4;
            float vv[4] = {v.x, v.y, v.z, v.w};
            #pragma unroll
            for (int e = 0; e < 4; e++) {
                int l = lin + e;
                int r = l / NF;
                int c = l - r * NF;
                ((float*)(tile + (r >> 1) * 64 + (c + 1)))[r & 1] = vv[e];
            }
        }
    } else {
        for (int i = tid; i < PAIRS * 64; i += BLOCK) tile[i] = 0;  // zero-fill tail block
        __syncthreads();
        for (int l = tid; l < rows * NF; l += BLOCK) {
            int r = l / NF, c = l - r * NF;
            ((float*)(tile + (r >> 1) * 64 + (c + 1)))[r & 1] = xc_blk[l];
        }
    }
    __syncthreads();

    // ---- quantum feature: <Z0> = cos(x1+p1)*cos(x2+p2) (qubit 0 cancels) ----
    const float qp1 = q_params[1], qp2 = q_params[2];
    if (tid < PAIRS) {
        int rA = 2 * tid, rB = 2 * tid + 1;
        float qA = __cosf(xqs[rA * 3 + 1] + qp1) * __cosf(xqs[rA * 3 + 2] + qp2);
        float qB = __cosf(xqs[rB * 3 + 1] + qp1) * __cosf(xqs[rB * 3 + 2] + qp2);
        tile[tid * 64] = pack2(qA, qB);
    }

    // ---- load layer-1 weight row + biases into registers ----
    float w1r[64];
    #pragma unroll
    for (int j = 0; j < 64; j++) w1r[j] = w1s[lane * 65 + j];  // (65l+j)%32 conflict-free
    const float b1v = b1[lane];
    const float b3v = b3[0];
    __syncthreads();

    // ---- compute: 2 pairs (4 rows) per sweep per warp ----
    const int o16 = lane & 15;
    const int psel = lane >> 4;

    #pragma unroll 1
    for (int s = 0; s < SWEEPS; s++) {
        const int p0 = warp * PPW + 2 * s;
        const int p1 = p0 + 1;
        const u64* t0 = tile + p0 * 64;
        const u64* t1 = tile + p1 * 64;

        // ---- layer 1: lane = output neuron; 2 chains per pair ----
        u64 a0a = dup2(b1v), a0b = 0;
        u64 a1a = dup2(b1v), a1b = 0;
        #pragma unroll
        for (int j = 0; j < 64; j += 2) {
            ulonglong2 c0 = *(const ulonglong2*)(t0 + j);   // broadcast LDS.128
            ulonglong2 c1 = *(const ulonglong2*)(t1 + j);
            u64 wd0 = dup2(w1r[j]);
            u64 wd1 = dup2(w1r[j + 1]);
            a0a = ffma2(c0.x, wd0, a0a);
            a0b = ffma2(c0.y, wd1, a0b);
            a1a = ffma2(c1.x, wd0, a1a);
            a1b = ffma2(c1.y, wd1, a1b);
        }
        u64 h0 = relu2(add2(a0a, a0b));
        u64 h1 = relu2(add2(a1a, a1b));
        htile[p0 * 32 + lane] = h0;                         // STS.64
        htile[p1 * 32 + lane] = h1;
        __syncwarp();

        // ---- layer 2: lanes 0-15 -> pair p0, lanes 16-31 -> pair p1 ----
        const u64* hb = htile + (p0 + psel) * 32;
        u64 ya = b2s[o16], yb = 0;
        #pragma unroll
        for (int j = 0; j < 32; j += 2) {
            ulonglong2 h2 = *(const ulonglong2*)(hb + j);   // half-warp-uniform LDS.128
            ya = ffma2(h2.x, w2s[j * 16 + o16], ya);
            yb = ffma2(h2.y, w2s[(j + 1) * 16 + o16], yb);
        }
        u64 y2 = relu2(add2(ya, yb));

        // ---- layer 3: multiply by w3[o], butterfly-reduce over 16 lanes ----
        u64 t = mul2(y2, w3s[o16]);
        float sa, sb; unpack2(t, sa, sb);
        #pragma unroll
        for (int m = 8; m >= 1; m >>= 1) {
            sa += __shfl_xor_sync(0xffffffffu, sa, m);
            sb += __shfl_xor_sync(0xffffffffu, sb, m);
        }
        if (o16 == 0) {
            long gr = base + 2L * (p0 + psel);
            if (gr + 1 < B) {
                *(float2*)(out + gr) = make_float2(sa + b3v, sb + b3v);
            } else if (gr < B) {
                out[gr] = sa + b3v;
            }
        }
        __syncwarp();
    }
}

extern "C" void kernel_launch(void* const* d_in, const int* in_sizes, int n_in,
                              void* d_out, int out_size) {
    const float* x_q = (const float*)d_in[0];
    const float* x_c = (const float*)d_in[1];
    const float* qp  = (const float*)d_in[2];
    const float* w1  = (const float*)d_in[3];
    const float* b1  = (const float*)d_in[4];
    const float* w2  = (const float*)d_in[5];
    const float* b2  = (const float*)d_in[6];
    const float* w3  = (const float*)d_in[7];
    const float* b3  = (const float*)d_in[8];

    int B = in_sizes[0] / 3;

    cudaFuncSetAttribute(hybrid_mlp_kernel,
                         cudaFuncAttributeMaxDynamicSharedMemorySize, SMEM_TOTAL);

    int nblk = (B + ROWS - 1) / ROWS;
    hybrid_mlp_kernel<<<nblk, BLOCK, SMEM_TOTAL>>>(x_q, x_c, qp, w1, b1, w2, b2, w3, b3,
                                                   (float*)d_out, B);
}